// round 1
// baseline (speedup 1.0000x reference)
#include <cuda_runtime.h>

#define NN 50000
#define NE 800000
#define HH 256
#define MC 8

// Scratch (no allocation allowed in kernel_launch).
__device__ __align__(256) float d_h [NN * HH];
__device__ __align__(256) float d_f1[NN * HH];
__device__ __align__(256) float d_f2[NN * HH];
__device__ __align__(256) float d_inv[NN];

// ---------- packed f32x2 helpers (2x FFMA throughput on sm_103a) ----------
__device__ __forceinline__ unsigned long long pk2(float lo, float hi) {
    unsigned long long r;
    asm("mov.b64 %0, {%1,%2};" : "=l"(r) : "f"(lo), "f"(hi));
    return r;
}
__device__ __forceinline__ void fma2(unsigned long long& d, unsigned long long a, unsigned long long b) {
    asm("fma.rn.f32x2 %0, %1, %2, %0;" : "+l"(d) : "l"(a), "l"(b));
}
__device__ __forceinline__ float2 up2(unsigned long long v) {
    float2 f;
    asm("mov.b64 {%0,%1}, %2;" : "=f"(f.x), "=f"(f.y) : "l"(v));
    return f;
}

// ---------- degree / normalization ----------
__global__ void k_deg_init(float* inv) {
    int i = blockIdx.x * blockDim.x + threadIdx.x;
    if (i < NN) inv[i] = 1.0f;                    // self loop
}
__global__ void k_deg_count(const int* __restrict__ dst, float* inv) {
    int e = blockIdx.x * blockDim.x + threadIdx.x;
    if (e < NE) atomicAdd(&inv[dst[e]], 1.0f);
}
__global__ void k_deg_fin(float* inv) {
    int i = blockIdx.x * blockDim.x + threadIdx.x;
    if (i < NN) inv[i] = rsqrtf(inv[i]);          // deg >= 1 guaranteed
}

// ---------- elementwise ----------
// out[i][c] = bias[c] + inv[i]^2 * h[i][c]   (self-loop term + bias)
__global__ void k_agg_init(const float4* __restrict__ h, const float* __restrict__ bias,
                           const float* __restrict__ inv, float4* __restrict__ out) {
    int idx = blockIdx.x * blockDim.x + threadIdx.x;   // over NN*64 float4
    if (idx >= NN * 64) return;
    int i = idx >> 6, c4 = idx & 63;
    float s = inv[i]; s = s * s;
    float4 hv = h[idx];
    float4 bv = *reinterpret_cast<const float4*>(&bias[c4 * 4]);
    out[idx] = make_float4(bv.x + s * hv.x, bv.y + s * hv.y,
                           bv.z + s * hv.z, bv.w + s * hv.w);
}

__global__ void k_relu(float4* f) {
    int idx = blockIdx.x * blockDim.x + threadIdx.x;
    if (idx >= NN * 64) return;
    float4 v = f[idx];
    v.x = fmaxf(v.x, 0.f); v.y = fmaxf(v.y, 0.f);
    v.z = fmaxf(v.z, 0.f); v.w = fmaxf(v.w, 0.f);
    f[idx] = v;
}

// ---------- edge scatter: out[dst] += inv[src]*inv[dst] * h[src] ----------
__global__ void k_agg_edges(const int* __restrict__ src, const int* __restrict__ dst,
                            const float* __restrict__ inv, const float* __restrict__ h,
                            float* __restrict__ out) {
    __shared__ int ss, dd;
    __shared__ float cf;
    int e = blockIdx.x;
    if (threadIdx.x == 0) {
        int s = src[e], d = dst[e];
        ss = s; dd = d;
        cf = inv[s] * inv[d];
    }
    __syncthreads();
    int c = threadIdx.x;
    atomicAdd(&out[dd * HH + c], cf * h[ss * HH + c]);
}

// ---------- SGEMM: C[M,256] = A[M,256] @ B[256,256], f32x2 micro-kernel ----------
__global__ __launch_bounds__(256) void sgemm_nn(const float* __restrict__ A,
                                                const float* __restrict__ B,
                                                float* __restrict__ C, int M) {
    __shared__ __align__(16) float As[16][132];
    __shared__ __align__(16) float Bs[16][128];
    const int m0 = blockIdx.x * 128;
    const int n0 = blockIdx.y * 128;
    const int tid = threadIdx.x;
    const int tx = tid & 15, ty = tid >> 4;

    unsigned long long acc[8][4];
#pragma unroll
    for (int i = 0; i < 8; i++)
#pragma unroll
        for (int p = 0; p < 4; p++) acc[i][p] = 0ULL;

    for (int k0 = 0; k0 < 256; k0 += 16) {
#pragma unroll
        for (int s = 0; s < 2; s++) {
            int id = tid + s * 256;              // 0..511
            int r = id >> 2, c4 = id & 3;
            int gm = m0 + r;
            float4 v = make_float4(0.f, 0.f, 0.f, 0.f);
            if (gm < M) v = *reinterpret_cast<const float4*>(&A[gm * 256 + k0 + c4 * 4]);
            As[c4 * 4 + 0][r] = v.x; As[c4 * 4 + 1][r] = v.y;
            As[c4 * 4 + 2][r] = v.z; As[c4 * 4 + 3][r] = v.w;
        }
#pragma unroll
        for (int s = 0; s < 2; s++) {
            int id = tid + s * 256;
            int kt = id >> 5, c4 = id & 31;
            float4 v = *reinterpret_cast<const float4*>(&B[(k0 + kt) * 256 + n0 + c4 * 4]);
            *reinterpret_cast<float4*>(&Bs[kt][c4 * 4]) = v;
        }
        __syncthreads();
#pragma unroll
        for (int kt = 0; kt < 16; kt++) {
            float4 a0 = *reinterpret_cast<const float4*>(&As[kt][ty * 8]);
            float4 a1 = *reinterpret_cast<const float4*>(&As[kt][ty * 8 + 4]);
            float4 b0 = *reinterpret_cast<const float4*>(&Bs[kt][tx * 8]);
            float4 b1 = *reinterpret_cast<const float4*>(&Bs[kt][tx * 8 + 4]);
            unsigned long long bb0 = pk2(b0.x, b0.y), bb1 = pk2(b0.z, b0.w);
            unsigned long long bb2 = pk2(b1.x, b1.y), bb3 = pk2(b1.z, b1.w);
            float av[8] = {a0.x, a0.y, a0.z, a0.w, a1.x, a1.y, a1.z, a1.w};
#pragma unroll
            for (int i = 0; i < 8; i++) {
                unsigned long long aa = pk2(av[i], av[i]);
                fma2(acc[i][0], aa, bb0);
                fma2(acc[i][1], aa, bb1);
                fma2(acc[i][2], aa, bb2);
                fma2(acc[i][3], aa, bb3);
            }
        }
        __syncthreads();
    }
#pragma unroll
    for (int i = 0; i < 8; i++) {
        int gm = m0 + ty * 8 + i;
        if (gm >= M) continue;
        float2 v0 = up2(acc[i][0]), v1 = up2(acc[i][1]);
        float2 v2 = up2(acc[i][2]), v3 = up2(acc[i][3]);
        *reinterpret_cast<float4*>(&C[gm * 256 + n0 + tx * 8]) =
            make_float4(v0.x, v0.y, v1.x, v1.y);
        *reinterpret_cast<float4*>(&C[gm * 256 + n0 + tx * 8 + 4]) =
            make_float4(v2.x, v2.y, v3.x, v3.y);
    }
}

// ---------- fused resize: out = feat * (gather(feat) @ resize_W + rb) ----------
// A row i, K index k=j*256+kk : (j < len[i]) ? feat[label[i][j]][kk] : 0
__global__ __launch_bounds__(256) void sgemm_gather(const float* __restrict__ feat,
                                                    const int* __restrict__ label,
                                                    const int* __restrict__ clen,
                                                    const float* __restrict__ Wr,
                                                    const float* __restrict__ rb,
                                                    float* __restrict__ out, int M) {
    __shared__ __align__(16) float As[16][132];
    __shared__ __align__(16) float Bs[16][128];
    __shared__ int lbl[128 * MC];
    __shared__ int lens[128];
    __shared__ int maxl;
    const int m0 = blockIdx.x * 128;
    const int n0 = blockIdx.y * 128;
    const int tid = threadIdx.x;
    const int tx = tid & 15, ty = tid >> 4;

    if (tid == 0) maxl = 0;
    __syncthreads();
    if (tid < 128) {
        int gm = m0 + tid;
        int L = (gm < M) ? clen[gm] : 0;
        lens[tid] = L;
        atomicMax(&maxl, L);
    }
#pragma unroll
    for (int s = 0; s < 4; s++) {
        int id = tid + s * 256;                   // 0..1023
        int r = id >> 3, j = id & 7;
        int gm = m0 + r;
        lbl[r * MC + j] = (gm < M) ? label[gm * MC + j] : 0;
    }
    __syncthreads();
    const int ML = maxl;                          // <= 7 in practice -> j=7 skipped

    unsigned long long acc[8][4];
#pragma unroll
    for (int i = 0; i < 8; i++)
#pragma unroll
        for (int p = 0; p < 4; p++) acc[i][p] = 0ULL;

    for (int j = 0; j < ML; j++) {
        for (int kk0 = 0; kk0 < 256; kk0 += 16) {
#pragma unroll
            for (int s = 0; s < 2; s++) {
                int id = tid + s * 256;
                int r = id >> 2, c4 = id & 3;
                float4 v = make_float4(0.f, 0.f, 0.f, 0.f);
                if (j < lens[r]) {
                    int isrc = lbl[r * MC + j];
                    v = *reinterpret_cast<const float4*>(&feat[isrc * 256 + kk0 + c4 * 4]);
                }
                As[c4 * 4 + 0][r] = v.x; As[c4 * 4 + 1][r] = v.y;
                As[c4 * 4 + 2][r] = v.z; As[c4 * 4 + 3][r] = v.w;
            }
#pragma unroll
            for (int s = 0; s < 2; s++) {
                int id = tid + s * 256;
                int kt = id >> 5, c4 = id & 31;
                float4 v = *reinterpret_cast<const float4*>(
                    &Wr[(j * 256 + kk0 + kt) * 256 + n0 + c4 * 4]);
                *reinterpret_cast<float4*>(&Bs[kt][c4 * 4]) = v;
            }
            __syncthreads();
#pragma unroll
            for (int kt = 0; kt < 16; kt++) {
                float4 a0 = *reinterpret_cast<const float4*>(&As[kt][ty * 8]);
                float4 a1 = *reinterpret_cast<const float4*>(&As[kt][ty * 8 + 4]);
                float4 b0 = *reinterpret_cast<const float4*>(&Bs[kt][tx * 8]);
                float4 b1 = *reinterpret_cast<const float4*>(&Bs[kt][tx * 8 + 4]);
                unsigned long long bb0 = pk2(b0.x, b0.y), bb1 = pk2(b0.z, b0.w);
                unsigned long long bb2 = pk2(b1.x, b1.y), bb3 = pk2(b1.z, b1.w);
                float av[8] = {a0.x, a0.y, a0.z, a0.w, a1.x, a1.y, a1.z, a1.w};
#pragma unroll
                for (int i = 0; i < 8; i++) {
                    unsigned long long aa = pk2(av[i], av[i]);
                    fma2(acc[i][0], aa, bb0);
                    fma2(acc[i][1], aa, bb1);
                    fma2(acc[i][2], aa, bb2);
                    fma2(acc[i][3], aa, bb3);
                }
            }
            __syncthreads();
        }
    }
    // epilogue: ctx = acc + rb;  out = feat * ctx
#pragma unroll
    for (int i = 0; i < 8; i++) {
        int gm = m0 + ty * 8 + i;
        if (gm >= M) continue;
        int cb = n0 + tx * 8;
        float2 v0 = up2(acc[i][0]), v1 = up2(acc[i][1]);
        float2 v2 = up2(acc[i][2]), v3 = up2(acc[i][3]);
        float4 rb0 = *reinterpret_cast<const float4*>(&rb[cb]);
        float4 rb1 = *reinterpret_cast<const float4*>(&rb[cb + 4]);
        float4 f0 = *reinterpret_cast<const float4*>(&feat[gm * 256 + cb]);
        float4 f1 = *reinterpret_cast<const float4*>(&feat[gm * 256 + cb + 4]);
        *reinterpret_cast<float4*>(&out[gm * 256 + cb]) =
            make_float4((v0.x + rb0.x) * f0.x, (v0.y + rb0.y) * f0.y,
                        (v1.x + rb0.z) * f0.z, (v1.y + rb0.w) * f0.w);
        *reinterpret_cast<float4*>(&out[gm * 256 + cb + 4]) =
            make_float4((v2.x + rb1.x) * f1.x, (v2.y + rb1.y) * f1.y,
                        (v3.x + rb1.z) * f1.z, (v3.y + rb1.w) * f1.w);
    }
}

extern "C" void kernel_launch(void* const* d_in, const int* in_sizes, int n_in,
                              void* d_out, int out_size) {
    const float* x    = (const float*)d_in[0];
    const int*   ei   = (const int*)d_in[1];
    const int*   lbl  = (const int*)d_in[2];
    const int*   clen = (const int*)d_in[3];
    const float* gW   = (const float*)d_in[4];
    const float* gb   = (const float*)d_in[5];
    const float* rW   = (const float*)d_in[6];
    const float* rb   = (const float*)d_in[7];
    float* out = (float*)d_out;

    const int* src = ei;
    const int* dst = ei + NE;

    float *h, *f1, *f2, *inv;
    cudaGetSymbolAddress((void**)&h,  d_h);
    cudaGetSymbolAddress((void**)&f1, d_f1);
    cudaGetSymbolAddress((void**)&f2, d_f2);
    cudaGetSymbolAddress((void**)&inv, d_inv);

    const int ELEM_BLK = 256;
    const int n_node_blk = (NN + ELEM_BLK - 1) / ELEM_BLK;
    const int n_vec_blk  = (NN * 64 + ELEM_BLK - 1) / ELEM_BLK;
    const dim3 gemm_grid((NN + 127) / 128, 2);

    // degree -> inv_sqrt
    k_deg_init<<<n_node_blk, ELEM_BLK>>>(inv);
    k_deg_count<<<(NE + ELEM_BLK - 1) / ELEM_BLK, ELEM_BLK>>>(dst, inv);
    k_deg_fin<<<n_node_blk, ELEM_BLK>>>(inv);

    // layer 1: h = x @ W ; f1 = b + selfloop + scatter ; relu
    sgemm_nn<<<gemm_grid, 256>>>(x, gW, h, NN);
    k_agg_init<<<n_vec_blk, ELEM_BLK>>>((const float4*)h, gb, inv, (float4*)f1);
    k_agg_edges<<<NE, 256>>>(src, dst, inv, h, f1);
    k_relu<<<n_vec_blk, ELEM_BLK>>>((float4*)f1);

    // layer 2: h = f1 @ W ; f2 = b + selfloop + scatter
    sgemm_nn<<<gemm_grid, 256>>>(f1, gW, h, NN);
    k_agg_init<<<n_vec_blk, ELEM_BLK>>>((const float4*)h, gb, inv, (float4*)f2);
    k_agg_edges<<<NE, 256>>>(src, dst, inv, h, f2);

    // fused context-gather resize GEMM + final elementwise product
    sgemm_gather<<<gemm_grid, 256>>>(f2, lbl, clen, rW, rb, out, NN);
}

// round 2
// speedup vs baseline: 1.7932x; 1.7932x over previous
#include <cuda_runtime.h>

#define NN 50000
#define NE 800000
#define HH 256
#define MC 8

// Scratch (no allocation allowed).
__device__ __align__(256) float d_h [NN * HH];
__device__ __align__(256) float d_f1[NN * HH];
__device__ __align__(256) float d_f2[NN * HH];
__device__ __align__(256) float d_inv[NN];
__device__ __align__(256) int   d_cnt[NN];
__device__ __align__(256) int   d_offs[NN];
__device__ __align__(256) int   d_fill[NN];
__device__ __align__(256) int   d_csrs[NE];
__device__ __align__(256) float d_csrc[NE];

// ---------- packed f32x2 helpers ----------
__device__ __forceinline__ unsigned long long pk2(float lo, float hi) {
    unsigned long long r;
    asm("mov.b64 %0, {%1,%2};" : "=l"(r) : "f"(lo), "f"(hi));
    return r;
}
__device__ __forceinline__ void fma2(unsigned long long& d, unsigned long long a, unsigned long long b) {
    asm("fma.rn.f32x2 %0, %1, %2, %0;" : "+l"(d) : "l"(a), "l"(b));
}
__device__ __forceinline__ float2 up2(unsigned long long v) {
    float2 f;
    asm("mov.b64 {%0,%1}, %2;" : "=f"(f.x), "=f"(f.y) : "l"(v));
    return f;
}

// ---------- CSR build ----------
__global__ void k_zero(int* cnt, int* fill) {
    int i = blockIdx.x * blockDim.x + threadIdx.x;
    if (i < NN) { cnt[i] = 0; fill[i] = 0; }
}
__global__ void k_count(const int* __restrict__ dst, int* cnt) {
    int e = blockIdx.x * blockDim.x + threadIdx.x;
    if (e < NE) atomicAdd(&cnt[dst[e]], 1);
}
__global__ void k_scan(const int* __restrict__ cnt, int* __restrict__ offs) {
    __shared__ int sh[1024];
    __shared__ int carry;
    int tid = threadIdx.x;
    if (tid == 0) carry = 0;
    __syncthreads();
    for (int base = 0; base < NN; base += 1024) {
        int v = (base + tid < NN) ? cnt[base + tid] : 0;
        sh[tid] = v;
        __syncthreads();
        for (int off = 1; off < 1024; off <<= 1) {
            int t = (tid >= off) ? sh[tid - off] : 0;
            __syncthreads();
            sh[tid] += t;
            __syncthreads();
        }
        if (base + tid < NN) offs[base + tid] = carry + sh[tid] - v;  // exclusive
        __syncthreads();
        if (tid == 0) carry += sh[1023];
        __syncthreads();
    }
}
__global__ void k_invdeg(const int* __restrict__ cnt, float* inv) {
    int i = blockIdx.x * blockDim.x + threadIdx.x;
    if (i < NN) inv[i] = rsqrtf((float)cnt[i] + 1.0f);   // +1 self loop
}
__global__ void k_fill(const int* __restrict__ src, const int* __restrict__ dst,
                       const float* __restrict__ inv, const int* __restrict__ offs,
                       int* fill, int* __restrict__ csrs, float* __restrict__ csrc) {
    int e = blockIdx.x * blockDim.x + threadIdx.x;
    if (e >= NE) return;
    int s = src[e], d = dst[e];
    int pos = offs[d] + atomicAdd(&fill[d], 1);
    csrs[pos] = s;
    csrc[pos] = inv[s] * inv[d];
}

// ---------- fused aggregation: out[i] = (relu?)(bias + inv[i]^2*h[i] + sum cf*h[src]) ----------
__global__ __launch_bounds__(256) void k_aggregate(
        const float* __restrict__ h, const float* __restrict__ bias,
        const float* __restrict__ inv, const int* __restrict__ offs,
        const int* __restrict__ cnt, const int* __restrict__ csrs,
        const float* __restrict__ csrc, float* __restrict__ out, int do_relu) {
    int gw = (blockIdx.x * blockDim.x + threadIdx.x) >> 5;
    if (gw >= NN) return;
    int lane = threadIdx.x & 31;
    int c = lane * 8;
    float s = inv[gw]; float sl = s * s;
    float4 h0 = *(const float4*)&h[gw * 256 + c];
    float4 h1 = *(const float4*)&h[gw * 256 + c + 4];
    float4 b0 = *(const float4*)&bias[c];
    float4 b1 = *(const float4*)&bias[c + 4];
    float4 A0 = make_float4(b0.x + sl * h0.x, b0.y + sl * h0.y,
                            b0.z + sl * h0.z, b0.w + sl * h0.w);
    float4 A1 = make_float4(b1.x + sl * h1.x, b1.y + sl * h1.y,
                            b1.z + sl * h1.z, b1.w + sl * h1.w);
    int beg = offs[gw], num = cnt[gw];
    for (int p0 = 0; p0 < num; p0 += 32) {
        int rem = num - p0;
        int sv = 0; float cf = 0.f;
        if (lane < rem) {
            sv = csrs[beg + p0 + lane];
            cf = csrc[beg + p0 + lane];
        }
        int lim = rem < 32 ? rem : 32;
        for (int k = 0; k < lim; k++) {
            int ss = __shfl_sync(0xffffffffu, sv, k);
            float cc = __shfl_sync(0xffffffffu, cf, k);
            float4 v0 = *(const float4*)&h[ss * 256 + c];
            float4 v1 = *(const float4*)&h[ss * 256 + c + 4];
            A0.x += cc * v0.x; A0.y += cc * v0.y; A0.z += cc * v0.z; A0.w += cc * v0.w;
            A1.x += cc * v1.x; A1.y += cc * v1.y; A1.z += cc * v1.z; A1.w += cc * v1.w;
        }
    }
    if (do_relu) {
        A0.x = fmaxf(A0.x, 0.f); A0.y = fmaxf(A0.y, 0.f);
        A0.z = fmaxf(A0.z, 0.f); A0.w = fmaxf(A0.w, 0.f);
        A1.x = fmaxf(A1.x, 0.f); A1.y = fmaxf(A1.y, 0.f);
        A1.z = fmaxf(A1.z, 0.f); A1.w = fmaxf(A1.w, 0.f);
    }
    *(float4*)&out[gw * 256 + c]     = A0;
    *(float4*)&out[gw * 256 + c + 4] = A1;
}

// ---------- double-buffered SGEMM: C[M,256] = A[M,256] @ B[256,256] ----------
__global__ __launch_bounds__(256, 2) void sgemm_nn(const float* __restrict__ A,
                                                   const float* __restrict__ B,
                                                   float* __restrict__ C, int M) {
    __shared__ __align__(16) float As[2][16][132];
    __shared__ __align__(16) float Bs[2][16][128];
    const int m0 = blockIdx.x * 128;
    const int n0 = blockIdx.y * 128;
    const int tid = threadIdx.x;
    const int tx = tid & 15, ty = tid >> 4;
    // A-load mapping (x2 segments), B-load mapping (x2 segments)
    const int rA0 = tid >> 2,            c4A0 = tid & 3;
    const int rA1 = (tid + 256) >> 2,    c4A1 = tid & 3;
    const int ktB0 = tid >> 5,           c4B0 = tid & 31;
    const int ktB1 = (tid + 256) >> 5,   c4B1 = tid & 31;

    unsigned long long acc[8][4];
#pragma unroll
    for (int i = 0; i < 8; i++)
#pragma unroll
        for (int p = 0; p < 4; p++) acc[i][p] = 0ULL;

    float4 stA0, stA1, stB0, stB1;
    // prologue: tile 0
    {
        int gm0 = m0 + rA0, gm1 = m0 + rA1;
        stA0 = (gm0 < M) ? *(const float4*)&A[gm0 * 256 + c4A0 * 4] : make_float4(0,0,0,0);
        stA1 = (gm1 < M) ? *(const float4*)&A[gm1 * 256 + c4A1 * 4] : make_float4(0,0,0,0);
        stB0 = *(const float4*)&B[ktB0 * 256 + n0 + c4B0 * 4];
        stB1 = *(const float4*)&B[ktB1 * 256 + n0 + c4B1 * 4];
        As[0][c4A0 * 4 + 0][rA0] = stA0.x; As[0][c4A0 * 4 + 1][rA0] = stA0.y;
        As[0][c4A0 * 4 + 2][rA0] = stA0.z; As[0][c4A0 * 4 + 3][rA0] = stA0.w;
        As[0][c4A1 * 4 + 0][rA1] = stA1.x; As[0][c4A1 * 4 + 1][rA1] = stA1.y;
        As[0][c4A1 * 4 + 2][rA1] = stA1.z; As[0][c4A1 * 4 + 3][rA1] = stA1.w;
        *(float4*)&Bs[0][ktB0][c4B0 * 4] = stB0;
        *(float4*)&Bs[0][ktB1][c4B1 * 4] = stB1;
    }
    __syncthreads();

    for (int t = 0; t < 16; t++) {
        const int cur = t & 1, nxt = cur ^ 1;
        if (t < 15) {
            int k0 = (t + 1) * 16;
            int gm0 = m0 + rA0, gm1 = m0 + rA1;
            stA0 = (gm0 < M) ? *(const float4*)&A[gm0 * 256 + k0 + c4A0 * 4] : make_float4(0,0,0,0);
            stA1 = (gm1 < M) ? *(const float4*)&A[gm1 * 256 + k0 + c4A1 * 4] : make_float4(0,0,0,0);
            stB0 = *(const float4*)&B[(k0 + ktB0) * 256 + n0 + c4B0 * 4];
            stB1 = *(const float4*)&B[(k0 + ktB1) * 256 + n0 + c4B1 * 4];
        }
#pragma unroll
        for (int kt = 0; kt < 16; kt++) {
            float4 a0 = *(const float4*)&As[cur][kt][ty * 8];
            float4 a1 = *(const float4*)&As[cur][kt][ty * 8 + 4];
            ulonglong2 bp0 = *(const ulonglong2*)&Bs[cur][kt][tx * 8];
            ulonglong2 bp1 = *(const ulonglong2*)&Bs[cur][kt][tx * 8 + 4];
            float av[8] = {a0.x, a0.y, a0.z, a0.w, a1.x, a1.y, a1.z, a1.w};
#pragma unroll
            for (int i = 0; i < 8; i++) {
                unsigned long long aa = pk2(av[i], av[i]);
                fma2(acc[i][0], aa, bp0.x);
                fma2(acc[i][1], aa, bp0.y);
                fma2(acc[i][2], aa, bp1.x);
                fma2(acc[i][3], aa, bp1.y);
            }
        }
        if (t < 15) {
            As[nxt][c4A0 * 4 + 0][rA0] = stA0.x; As[nxt][c4A0 * 4 + 1][rA0] = stA0.y;
            As[nxt][c4A0 * 4 + 2][rA0] = stA0.z; As[nxt][c4A0 * 4 + 3][rA0] = stA0.w;
            As[nxt][c4A1 * 4 + 0][rA1] = stA1.x; As[nxt][c4A1 * 4 + 1][rA1] = stA1.y;
            As[nxt][c4A1 * 4 + 2][rA1] = stA1.z; As[nxt][c4A1 * 4 + 3][rA1] = stA1.w;
            *(float4*)&Bs[nxt][ktB0][c4B0 * 4] = stB0;
            *(float4*)&Bs[nxt][ktB1][c4B1 * 4] = stB1;
            __syncthreads();
        }
    }
#pragma unroll
    for (int i = 0; i < 8; i++) {
        int gm = m0 + ty * 8 + i;
        if (gm >= M) continue;
        float2 v0 = up2(acc[i][0]), v1 = up2(acc[i][1]);
        float2 v2 = up2(acc[i][2]), v3 = up2(acc[i][3]);
        *(float4*)&C[gm * 256 + n0 + tx * 8] = make_float4(v0.x, v0.y, v1.x, v1.y);
        *(float4*)&C[gm * 256 + n0 + tx * 8 + 4] = make_float4(v2.x, v2.y, v3.x, v3.y);
    }
}

// ---------- fused resize: out = feat * (gather(feat) @ resize_W + rb) ----------
__global__ __launch_bounds__(256, 2) void sgemm_gather(
        const float* __restrict__ feat, const int* __restrict__ label,
        const int* __restrict__ clen, const float* __restrict__ Wr,
        const float* __restrict__ rb, float* __restrict__ out, int M) {
    __shared__ __align__(16) float As[2][16][132];
    __shared__ __align__(16) float Bs[2][16][128];
    __shared__ int lbl[128 * MC];
    __shared__ int lens[128];
    __shared__ int maxl;
    const int m0 = blockIdx.x * 128;
    const int n0 = blockIdx.y * 128;
    const int tid = threadIdx.x;
    const int tx = tid & 15, ty = tid >> 4;
    const int rA0 = tid >> 2,          c4A0 = tid & 3;
    const int rA1 = (tid + 256) >> 2,  c4A1 = tid & 3;
    const int ktB0 = tid >> 5,         c4B0 = tid & 31;
    const int ktB1 = (tid + 256) >> 5, c4B1 = tid & 31;

    if (tid == 0) maxl = 0;
    __syncthreads();
    if (tid < 128) {
        int gm = m0 + tid;
        int L = (gm < M) ? clen[gm] : 0;
        lens[tid] = L;
        atomicMax(&maxl, L);
    }
#pragma unroll
    for (int s = 0; s < 4; s++) {
        int id = tid + s * 256;
        int r = id >> 3, j = id & 7;
        int gm = m0 + r;
        lbl[r * MC + j] = (gm < M) ? label[gm * MC + j] : 0;
    }
    __syncthreads();
    const int T = maxl * 16;           // flattened k-tiles (j, kk0)

    unsigned long long acc[8][4];
#pragma unroll
    for (int i = 0; i < 8; i++)
#pragma unroll
        for (int p = 0; p < 4; p++) acc[i][p] = 0ULL;

    if (T > 0) {
        float4 stA0, stA1, stB0, stB1;
        // prologue: tile 0 (j=0, kk0=0)
        {
            stA0 = (0 < lens[rA0]) ? *(const float4*)&feat[lbl[rA0 * MC] * 256 + c4A0 * 4]
                                   : make_float4(0,0,0,0);
            stA1 = (0 < lens[rA1]) ? *(const float4*)&feat[lbl[rA1 * MC] * 256 + c4A1 * 4]
                                   : make_float4(0,0,0,0);
            stB0 = *(const float4*)&Wr[ktB0 * 256 + n0 + c4B0 * 4];
            stB1 = *(const float4*)&Wr[ktB1 * 256 + n0 + c4B1 * 4];
            As[0][c4A0 * 4 + 0][rA0] = stA0.x; As[0][c4A0 * 4 + 1][rA0] = stA0.y;
            As[0][c4A0 * 4 + 2][rA0] = stA0.z; As[0][c4A0 * 4 + 3][rA0] = stA0.w;
            As[0][c4A1 * 4 + 0][rA1] = stA1.x; As[0][c4A1 * 4 + 1][rA1] = stA1.y;
            As[0][c4A1 * 4 + 2][rA1] = stA1.z; As[0][c4A1 * 4 + 3][rA1] = stA1.w;
            *(float4*)&Bs[0][ktB0][c4B0 * 4] = stB0;
            *(float4*)&Bs[0][ktB1][c4B1 * 4] = stB1;
        }
        __syncthreads();

        for (int t = 0; t < T; t++) {
            const int cur = t & 1, nxt = cur ^ 1;
            if (t + 1 < T) {
                int tn = t + 1;
                int j = tn >> 4, kk0 = (tn & 15) << 4;
                stA0 = (j < lens[rA0])
                     ? *(const float4*)&feat[lbl[rA0 * MC + j] * 256 + kk0 + c4A0 * 4]
                     : make_float4(0,0,0,0);
                stA1 = (j < lens[rA1])
                     ? *(const float4*)&feat[lbl[rA1 * MC + j] * 256 + kk0 + c4A1 * 4]
                     : make_float4(0,0,0,0);
                stB0 = *(const float4*)&Wr[(j * 256 + kk0 + ktB0) * 256 + n0 + c4B0 * 4];
                stB1 = *(const float4*)&Wr[(j * 256 + kk0 + ktB1) * 256 + n0 + c4B1 * 4];
            }
#pragma unroll
            for (int kt = 0; kt < 16; kt++) {
                float4 a0 = *(const float4*)&As[cur][kt][ty * 8];
                float4 a1 = *(const float4*)&As[cur][kt][ty * 8 + 4];
                ulonglong2 bp0 = *(const ulonglong2*)&Bs[cur][kt][tx * 8];
                ulonglong2 bp1 = *(const ulonglong2*)&Bs[cur][kt][tx * 8 + 4];
                float av[8] = {a0.x, a0.y, a0.z, a0.w, a1.x, a1.y, a1.z, a1.w};
#pragma unroll
                for (int i = 0; i < 8; i++) {
                    unsigned long long aa = pk2(av[i], av[i]);
                    fma2(acc[i][0], aa, bp0.x);
                    fma2(acc[i][1], aa, bp0.y);
                    fma2(acc[i][2], aa, bp1.x);
                    fma2(acc[i][3], aa, bp1.y);
                }
            }
            if (t + 1 < T) {
                As[nxt][c4A0 * 4 + 0][rA0] = stA0.x; As[nxt][c4A0 * 4 + 1][rA0] = stA0.y;
                As[nxt][c4A0 * 4 + 2][rA0] = stA0.z; As[nxt][c4A0 * 4 + 3][rA0] = stA0.w;
                As[nxt][c4A1 * 4 + 0][rA1] = stA1.x; As[nxt][c4A1 * 4 + 1][rA1] = stA1.y;
                As[nxt][c4A1 * 4 + 2][rA1] = stA1.z; As[nxt][c4A1 * 4 + 3][rA1] = stA1.w;
                *(float4*)&Bs[nxt][ktB0][c4B0 * 4] = stB0;
                *(float4*)&Bs[nxt][ktB1][c4B1 * 4] = stB1;
                __syncthreads();
            }
        }
    }
    // epilogue: ctx = acc + rb;  out = feat * ctx
#pragma unroll
    for (int i = 0; i < 8; i++) {
        int gm = m0 + ty * 8 + i;
        if (gm >= M) continue;
        int cb = n0 + tx * 8;
        float2 v0 = up2(acc[i][0]), v1 = up2(acc[i][1]);
        float2 v2 = up2(acc[i][2]), v3 = up2(acc[i][3]);
        float4 rb0 = *(const float4*)&rb[cb];
        float4 rb1 = *(const float4*)&rb[cb + 4];
        float4 f0 = *(const float4*)&feat[gm * 256 + cb];
        float4 f1 = *(const float4*)&feat[gm * 256 + cb + 4];
        *(float4*)&out[gm * 256 + cb] =
            make_float4((v0.x + rb0.x) * f0.x, (v0.y + rb0.y) * f0.y,
                        (v1.x + rb0.z) * f0.z, (v1.y + rb0.w) * f0.w);
        *(float4*)&out[gm * 256 + cb + 4] =
            make_float4((v2.x + rb1.x) * f1.x, (v2.y + rb1.y) * f1.y,
                        (v3.x + rb1.z) * f1.z, (v3.y + rb1.w) * f1.w);
    }
}

extern "C" void kernel_launch(void* const* d_in, const int* in_sizes, int n_in,
                              void* d_out, int out_size) {
    const float* x    = (const float*)d_in[0];
    const int*   ei   = (const int*)d_in[1];
    const int*   lbl  = (const int*)d_in[2];
    const int*   clen = (const int*)d_in[3];
    const float* gW   = (const float*)d_in[4];
    const float* gb   = (const float*)d_in[5];
    const float* rW   = (const float*)d_in[6];
    const float* rb   = (const float*)d_in[7];
    float* out = (float*)d_out;

    const int* src = ei;
    const int* dst = ei + NE;

    float *h, *f1, *f2, *inv, *csrc;
    int *cnt, *offs, *fill, *csrs;
    cudaGetSymbolAddress((void**)&h,    d_h);
    cudaGetSymbolAddress((void**)&f1,   d_f1);
    cudaGetSymbolAddress((void**)&f2,   d_f2);
    cudaGetSymbolAddress((void**)&inv,  d_inv);
    cudaGetSymbolAddress((void**)&cnt,  d_cnt);
    cudaGetSymbolAddress((void**)&offs, d_offs);
    cudaGetSymbolAddress((void**)&fill, d_fill);
    cudaGetSymbolAddress((void**)&csrs, d_csrs);
    cudaGetSymbolAddress((void**)&csrc, d_csrc);

    const int BLK = 256;
    const int n_node_blk = (NN + BLK - 1) / BLK;
    const int n_edge_blk = (NE + BLK - 1) / BLK;
    const dim3 gemm_grid((NN + 127) / 128, 2);
    const int agg_blk = (NN * 32 + BLK - 1) / BLK;   // warp per node

    // CSR build + normalization
    k_zero<<<n_node_blk, BLK>>>(cnt, fill);
    k_count<<<n_edge_blk, BLK>>>(dst, cnt);
    k_scan<<<1, 1024>>>(cnt, offs);
    k_invdeg<<<n_node_blk, BLK>>>(cnt, inv);
    k_fill<<<n_edge_blk, BLK>>>(src, dst, inv, offs, fill, csrs, csrc);

    // layer 1
    sgemm_nn<<<gemm_grid, 256>>>(x, gW, h, NN);
    k_aggregate<<<agg_blk, BLK>>>(h, gb, inv, offs, cnt, csrs, csrc, f1, 1);
    // layer 2
    sgemm_nn<<<gemm_grid, 256>>>(f1, gW, h, NN);
    k_aggregate<<<agg_blk, BLK>>>(h, gb, inv, offs, cnt, csrs, csrc, f2, 0);
    // fused context-gather resize GEMM + final product
    sgemm_gather<<<gemm_grid, 256>>>(f2, lbl, clen, rW, rb, out, NN);
}

// round 8
// speedup vs baseline: 2.2947x; 1.2797x over previous
#include <cuda_runtime.h>

#define NN 50000
#define NE 800000
#define HH 256
#define MC 8

// Scratch (no allocation allowed).
__device__ __align__(256) float d_h [NN * HH];
__device__ __align__(256) float d_f1[NN * HH];
__device__ __align__(256) float d_f2[NN * HH];
__device__ __align__(256) float d_inv[NN];
__device__ __align__(256) int   d_cnt[NN];
__device__ __align__(256) int   d_offs[NN];
__device__ __align__(256) int   d_fill[NN];
__device__ __align__(256) int   d_csrs[NE];
__device__ __align__(256) float d_csrc[NE];
__device__ __align__(256) int   d_perm[NN];
__device__ int d_lcnt[MC + 1];
__device__ int d_loff[MC + 1];
__device__ int d_lfill[MC + 1];

// ---------- packed f32x2 helpers ----------
__device__ __forceinline__ unsigned long long pk2(float lo, float hi) {
    unsigned long long r;
    asm("mov.b64 %0, {%1,%2};" : "=l"(r) : "f"(lo), "f"(hi));
    return r;
}
__device__ __forceinline__ void fma2(unsigned long long& d, unsigned long long a, unsigned long long b) {
    asm("fma.rn.f32x2 %0, %1, %2, %0;" : "+l"(d) : "l"(a), "l"(b));
}
__device__ __forceinline__ float2 up2(unsigned long long v) {
    float2 f;
    asm("mov.b64 {%0,%1}, %2;" : "=f"(f.x), "=f"(f.y) : "l"(v));
    return f;
}

// ---------- CSR build ----------
__global__ void k_zero(int* cnt, int* fill, int* lcnt, int* lfill) {
    int i = blockIdx.x * blockDim.x + threadIdx.x;
    if (i < NN) { cnt[i] = 0; fill[i] = 0; }
    if (i <= MC) { lcnt[i] = 0; lfill[i] = 0; }
}
__global__ void k_count(const int* __restrict__ dst, int* cnt) {
    int e = blockIdx.x * blockDim.x + threadIdx.x;
    if (e < NE) atomicAdd(&cnt[dst[e]], 1);
}
__global__ void k_scan(const int* __restrict__ cnt, int* __restrict__ offs) {
    __shared__ int sh[1024];
    __shared__ int carry;
    int tid = threadIdx.x;
    if (tid == 0) carry = 0;
    __syncthreads();
    for (int base = 0; base < NN; base += 1024) {
        int v = (base + tid < NN) ? cnt[base + tid] : 0;
        sh[tid] = v;
        __syncthreads();
        for (int off = 1; off < 1024; off <<= 1) {
            int t = (tid >= off) ? sh[tid - off] : 0;
            __syncthreads();
            sh[tid] += t;
            __syncthreads();
        }
        if (base + tid < NN) offs[base + tid] = carry + sh[tid] - v;  // exclusive
        __syncthreads();
        if (tid == 0) carry += sh[1023];
        __syncthreads();
    }
}
__global__ void k_invdeg(const int* __restrict__ cnt, float* inv) {
    int i = blockIdx.x * blockDim.x + threadIdx.x;
    if (i < NN) inv[i] = rsqrtf((float)cnt[i] + 1.0f);   // +1 self loop
}
__global__ void k_fill(const int* __restrict__ src, const int* __restrict__ dst,
                       const float* __restrict__ inv, const int* __restrict__ offs,
                       int* fill, int* __restrict__ csrs, float* __restrict__ csrc) {
    int e = blockIdx.x * blockDim.x + threadIdx.x;
    if (e >= NE) return;
    int s = src[e], d = dst[e];
    int pos = offs[d] + atomicAdd(&fill[d], 1);
    csrs[pos] = s;
    csrc[pos] = inv[s] * inv[d];
}

// ---------- length-bucket counting sort (perm groups rows by context_len) ----------
__global__ void k_lcount(const int* __restrict__ clen, int* lcnt) {
    int i = blockIdx.x * blockDim.x + threadIdx.x;
    if (i < NN) {
        int L = clen[i];
        if (L < 0) L = 0; if (L > MC) L = MC;
        atomicAdd(&lcnt[L], 1);
    }
}
__global__ void k_lscan(const int* __restrict__ lcnt, int* __restrict__ loff) {
    if (threadIdx.x == 0) {
        int acc = 0;
        for (int b = 0; b <= MC; b++) { loff[b] = acc; acc += lcnt[b]; }
    }
}
__global__ void k_lfill(const int* __restrict__ clen, const int* __restrict__ loff,
                        int* lfill, int* __restrict__ perm) {
    int i = blockIdx.x * blockDim.x + threadIdx.x;
    if (i < NN) {
        int L = clen[i];
        if (L < 0) L = 0; if (L > MC) L = MC;
        int pos = loff[L] + atomicAdd(&lfill[L], 1);
        perm[pos] = i;
    }
}

// ---------- fused aggregation: out[i] = (relu?)(bias + inv[i]^2*h[i] + sum cf*h[src]) ----------
__global__ __launch_bounds__(256) void k_aggregate(
        const float* __restrict__ h, const float* __restrict__ bias,
        const float* __restrict__ inv, const int* __restrict__ offs,
        const int* __restrict__ cnt, const int* __restrict__ csrs,
        const float* __restrict__ csrc, float* __restrict__ out, int do_relu) {
    int gw = (blockIdx.x * blockDim.x + threadIdx.x) >> 5;
    if (gw >= NN) return;
    int lane = threadIdx.x & 31;
    int c = lane * 8;
    float s = inv[gw]; float sl = s * s;
    float4 h0 = *(const float4*)&h[gw * 256 + c];
    float4 h1 = *(const float4*)&h[gw * 256 + c + 4];
    float4 b0 = *(const float4*)&bias[c];
    float4 b1 = *(const float4*)&bias[c + 4];
    float4 A0 = make_float4(b0.x + sl * h0.x, b0.y + sl * h0.y,
                            b0.z + sl * h0.z, b0.w + sl * h0.w);
    float4 A1 = make_float4(b1.x + sl * h1.x, b1.y + sl * h1.y,
                            b1.z + sl * h1.z, b1.w + sl * h1.w);
    int beg = offs[gw], num = cnt[gw];
    for (int p0 = 0; p0 < num; p0 += 32) {
        int rem = num - p0;
        int sv = 0; float cf = 0.f;
        if (lane < rem) {
            sv = csrs[beg + p0 + lane];
            cf = csrc[beg + p0 + lane];
        }
        int lim = rem < 32 ? rem : 32;
        for (int k = 0; k < lim; k++) {
            int ss = __shfl_sync(0xffffffffu, sv, k);
            float cc = __shfl_sync(0xffffffffu, cf, k);
            float4 v0 = *(const float4*)&h[ss * 256 + c];
            float4 v1 = *(const float4*)&h[ss * 256 + c + 4];
            A0.x += cc * v0.x; A0.y += cc * v0.y; A0.z += cc * v0.z; A0.w += cc * v0.w;
            A1.x += cc * v1.x; A1.y += cc * v1.y; A1.z += cc * v1.z; A1.w += cc * v1.w;
        }
    }
    if (do_relu) {
        A0.x = fmaxf(A0.x, 0.f); A0.y = fmaxf(A0.y, 0.f);
        A0.z = fmaxf(A0.z, 0.f); A0.w = fmaxf(A0.w, 0.f);
        A1.x = fmaxf(A1.x, 0.f); A1.y = fmaxf(A1.y, 0.f);
        A1.z = fmaxf(A1.z, 0.f); A1.w = fmaxf(A1.w, 0.f);
    }
    *(float4*)&out[gw * 256 + c]     = A0;
    *(float4*)&out[gw * 256 + c + 4] = A1;
}

// ---------- double-buffered SGEMM: C[M,256] = A[M,256] @ B[256,256] ----------
__global__ __launch_bounds__(256, 2) void sgemm_nn(const float* __restrict__ A,
                                                   const float* __restrict__ B,
                                                   float* __restrict__ C, int M) {
    __shared__ __align__(16) float As[2][16][132];
    __shared__ __align__(16) float Bs[2][16][128];
    const int m0 = blockIdx.x * 128;
    const int n0 = blockIdx.y * 128;
    const int tid = threadIdx.x;
    const int tx = tid & 15, ty = tid >> 4;
    const int rA0 = tid >> 2,            c4A0 = tid & 3;
    const int rA1 = (tid + 256) >> 2,    c4A1 = tid & 3;
    const int ktB0 = tid >> 5,           c4B0 = tid & 31;
    const int ktB1 = (tid + 256) >> 5,   c4B1 = tid & 31;

    unsigned long long acc[8][4];
#pragma unroll
    for (int i = 0; i < 8; i++)
#pragma unroll
        for (int p = 0; p < 4; p++) acc[i][p] = 0ULL;

    float4 stA0, stA1, stB0, stB1;
    {
        int gm0 = m0 + rA0, gm1 = m0 + rA1;
        stA0 = (gm0 < M) ? *(const float4*)&A[gm0 * 256 + c4A0 * 4] : make_float4(0,0,0,0);
        stA1 = (gm1 < M) ? *(const float4*)&A[gm1 * 256 + c4A1 * 4] : make_float4(0,0,0,0);
        stB0 = *(const float4*)&B[ktB0 * 256 + n0 + c4B0 * 4];
        stB1 = *(const float4*)&B[ktB1 * 256 + n0 + c4B1 * 4];
        As[0][c4A0 * 4 + 0][rA0] = stA0.x; As[0][c4A0 * 4 + 1][rA0] = stA0.y;
        As[0][c4A0 * 4 + 2][rA0] = stA0.z; As[0][c4A0 * 4 + 3][rA0] = stA0.w;
        As[0][c4A1 * 4 + 0][rA1] = stA1.x; As[0][c4A1 * 4 + 1][rA1] = stA1.y;
        As[0][c4A1 * 4 + 2][rA1] = stA1.z; As[0][c4A1 * 4 + 3][rA1] = stA1.w;
        *(float4*)&Bs[0][ktB0][c4B0 * 4] = stB0;
        *(float4*)&Bs[0][ktB1][c4B1 * 4] = stB1;
    }
    __syncthreads();

    for (int t = 0; t < 16; t++) {
        const int cur = t & 1, nxt = cur ^ 1;
        if (t < 15) {
            int k0 = (t + 1) * 16;
            int gm0 = m0 + rA0, gm1 = m0 + rA1;
            stA0 = (gm0 < M) ? *(const float4*)&A[gm0 * 256 + k0 + c4A0 * 4] : make_float4(0,0,0,0);
            stA1 = (gm1 < M) ? *(const float4*)&A[gm1 * 256 + k0 + c4A1 * 4] : make_float4(0,0,0,0);
            stB0 = *(const float4*)&B[(k0 + ktB0) * 256 + n0 + c4B0 * 4];
            stB1 = *(const float4*)&B[(k0 + ktB1) * 256 + n0 + c4B1 * 4];
        }
#pragma unroll
        for (int kt = 0; kt < 16; kt++) {
            float4 a0 = *(const float4*)&As[cur][kt][ty * 8];
            float4 a1 = *(const float4*)&As[cur][kt][ty * 8 + 4];
            ulonglong2 bp0 = *(const ulonglong2*)&Bs[cur][kt][tx * 8];
            ulonglong2 bp1 = *(const ulonglong2*)&Bs[cur][kt][tx * 8 + 4];
            float av[8] = {a0.x, a0.y, a0.z, a0.w, a1.x, a1.y, a1.z, a1.w};
#pragma unroll
            for (int i = 0; i < 8; i++) {
                unsigned long long aa = pk2(av[i], av[i]);
                fma2(acc[i][0], aa, bp0.x);
                fma2(acc[i][1], aa, bp0.y);
                fma2(acc[i][2], aa, bp1.x);
                fma2(acc[i][3], aa, bp1.y);
            }
        }
        if (t < 15) {
            As[nxt][c4A0 * 4 + 0][rA0] = stA0.x; As[nxt][c4A0 * 4 + 1][rA0] = stA0.y;
            As[nxt][c4A0 * 4 + 2][rA0] = stA0.z; As[nxt][c4A0 * 4 + 3][rA0] = stA0.w;
            As[nxt][c4A1 * 4 + 0][rA1] = stA1.x; As[nxt][c4A1 * 4 + 1][rA1] = stA1.y;
            As[nxt][c4A1 * 4 + 2][rA1] = stA1.z; As[nxt][c4A1 * 4 + 3][rA1] = stA1.w;
            *(float4*)&Bs[nxt][ktB0][c4B0 * 4] = stB0;
            *(float4*)&Bs[nxt][ktB1][c4B1 * 4] = stB1;
            __syncthreads();
        }
    }
#pragma unroll
    for (int i = 0; i < 8; i++) {
        int gm = m0 + ty * 8 + i;
        if (gm >= M) continue;
        float2 v0 = up2(acc[i][0]), v1 = up2(acc[i][1]);
        float2 v2 = up2(acc[i][2]), v3 = up2(acc[i][3]);
        *(float4*)&C[gm * 256 + n0 + tx * 8] = make_float4(v0.x, v0.y, v1.x, v1.y);
        *(float4*)&C[gm * 256 + n0 + tx * 8 + 4] = make_float4(v2.x, v2.y, v3.x, v3.y);
    }
}

// ---------- fused resize (length-sorted rows): out[p] = feat[p] * (gather(feat,p) @ Wr + rb) ----------
// Rows are processed in perm order: block covers perm[m0..m0+127], whose context
// lengths are (nearly) equal thanks to the counting sort -> blockmax ~= row len.
__global__ __launch_bounds__(256, 2) void sgemm_gather(
        const float* __restrict__ feat, const int* __restrict__ label,
        const int* __restrict__ clen, const int* __restrict__ perm,
        const float* __restrict__ Wr, const float* __restrict__ rb,
        float* __restrict__ out, int M) {
    __shared__ __align__(16) float As[2][16][132];
    __shared__ __align__(16) float Bs[2][16][128];
    __shared__ int lbl[128 * MC];
    __shared__ int lens[128];
    __shared__ int prow[128];
    __shared__ int maxl;
    const int m0 = blockIdx.x * 128;
    const int n0 = blockIdx.y * 128;
    const int tid = threadIdx.x;
    const int tx = tid & 15, ty = tid >> 4;
    const int rA0 = tid >> 2,          c4A0 = tid & 3;
    const int rA1 = (tid + 256) >> 2,  c4A1 = tid & 3;
    const int ktB0 = tid >> 5,         c4B0 = tid & 31;
    const int ktB1 = (tid + 256) >> 5, c4B1 = tid & 31;

    if (tid == 0) maxl = 0;
    __syncthreads();
    if (tid < 128) {
        int gm = m0 + tid;
        int p = (gm < M) ? perm[gm] : 0;
        prow[tid] = p;
        int L = (gm < M) ? clen[p] : 0;
        lens[tid] = L;
        atomicMax(&maxl, L);
    }
    __syncthreads();
#pragma unroll
    for (int s = 0; s < 4; s++) {
        int id = tid + s * 256;
        int r = id >> 3, j = id & 7;
        lbl[id] = (m0 + r < M) ? label[prow[r] * MC + j] : 0;
    }
    __syncthreads();
    const int T = maxl * 16;           // flattened k-tiles (j, kk0)

    unsigned long long acc[8][4];
#pragma unroll
    for (int i = 0; i < 8; i++)
#pragma unroll
        for (int p = 0; p < 4; p++) acc[i][p] = 0ULL;

    if (T > 0) {
        float4 stA0, stA1, stB0, stB1;
        {
            stA0 = (0 < lens[rA0]) ? *(const float4*)&feat[lbl[rA0 * MC] * 256 + c4A0 * 4]
                                   : make_float4(0,0,0,0);
            stA1 = (0 < lens[rA1]) ? *(const float4*)&feat[lbl[rA1 * MC] * 256 + c4A1 * 4]
                                   : make_float4(0,0,0,0);
            stB0 = *(const float4*)&Wr[ktB0 * 256 + n0 + c4B0 * 4];
            stB1 = *(const float4*)&Wr[ktB1 * 256 + n0 + c4B1 * 4];
            As[0][c4A0 * 4 + 0][rA0] = stA0.x; As[0][c4A0 * 4 + 1][rA0] = stA0.y;
            As[0][c4A0 * 4 + 2][rA0] = stA0.z; As[0][c4A0 * 4 + 3][rA0] = stA0.w;
            As[0][c4A1 * 4 + 0][rA1] = stA1.x; As[0][c4A1 * 4 + 1][rA1] = stA1.y;
            As[0][c4A1 * 4 + 2][rA1] = stA1.z; As[0][c4A1 * 4 + 3][rA1] = stA1.w;
            *(float4*)&Bs[0][ktB0][c4B0 * 4] = stB0;
            *(float4*)&Bs[0][ktB1][c4B1 * 4] = stB1;
        }
        __syncthreads();

        for (int t = 0; t < T; t++) {
            const int cur = t & 1, nxt = cur ^ 1;
            if (t + 1 < T) {
                int tn = t + 1;
                int j = tn >> 4, kk0 = (tn & 15) << 4;
                stA0 = (j < lens[rA0])
                     ? *(const float4*)&feat[lbl[rA0 * MC + j] * 256 + kk0 + c4A0 * 4]
                     : make_float4(0,0,0,0);
                stA1 = (j < lens[rA1])
                     ? *(const float4*)&feat[lbl[rA1 * MC + j] * 256 + kk0 + c4A1 * 4]
                     : make_float4(0,0,0,0);
                stB0 = *(const float4*)&Wr[(j * 256 + kk0 + ktB0) * 256 + n0 + c4B0 * 4];
                stB1 = *(const float4*)&Wr[(j * 256 + kk0 + ktB1) * 256 + n0 + c4B1 * 4];
            }
#pragma unroll
            for (int kt = 0; kt < 16; kt++) {
                float4 a0 = *(const float4*)&As[cur][kt][ty * 8];
                float4 a1 = *(const float4*)&As[cur][kt][ty * 8 + 4];
                ulonglong2 bp0 = *(const ulonglong2*)&Bs[cur][kt][tx * 8];
                ulonglong2 bp1 = *(const ulonglong2*)&Bs[cur][kt][tx * 8 + 4];
                float av[8] = {a0.x, a0.y, a0.z, a0.w, a1.x, a1.y, a1.z, a1.w};
#pragma unroll
                for (int i = 0; i < 8; i++) {
                    unsigned long long aa = pk2(av[i], av[i]);
                    fma2(acc[i][0], aa, bp0.x);
                    fma2(acc[i][1], aa, bp0.y);
                    fma2(acc[i][2], aa, bp1.x);
                    fma2(acc[i][3], aa, bp1.y);
                }
            }
            if (t + 1 < T) {
                As[nxt][c4A0 * 4 + 0][rA0] = stA0.x; As[nxt][c4A0 * 4 + 1][rA0] = stA0.y;
                As[nxt][c4A0 * 4 + 2][rA0] = stA0.z; As[nxt][c4A0 * 4 + 3][rA0] = stA0.w;
                As[nxt][c4A1 * 4 + 0][rA1] = stA1.x; As[nxt][c4A1 * 4 + 1][rA1] = stA1.y;
                As[nxt][c4A1 * 4 + 2][rA1] = stA1.z; As[nxt][c4A1 * 4 + 3][rA1] = stA1.w;
                *(float4*)&Bs[nxt][ktB0][c4B0 * 4] = stB0;
                *(float4*)&Bs[nxt][ktB1][c4B1 * 4] = stB1;
                __syncthreads();
            }
        }
    }
    // epilogue: ctx = acc + rb;  out[prow] = feat[prow] * ctx
#pragma unroll
    for (int i = 0; i < 8; i++) {
        int gm = m0 + ty * 8 + i;
        if (gm >= M) continue;
        int pr = prow[ty * 8 + i];
        int cb = n0 + tx * 8;
        float2 v0 = up2(acc[i][0]), v1 = up2(acc[i][1]);
        float2 v2 = up2(acc[i][2]), v3 = up2(acc[i][3]);
        float4 rb0 = *(const float4*)&rb[cb];
        float4 rb1 = *(const float4*)&rb[cb + 4];
        float4 f0 = *(const float4*)&feat[pr * 256 + cb];
        float4 f1 = *(const float4*)&feat[pr * 256 + cb + 4];
        *(float4*)&out[pr * 256 + cb] =
            make_float4((v0.x + rb0.x) * f0.x, (v0.y + rb0.y) * f0.y,
                        (v1.x + rb0.z) * f0.z, (v1.y + rb0.w) * f0.w);
        *(float4*)&out[pr * 256 + cb + 4] =
            make_float4((v2.x + rb1.x) * f1.x, (v2.y + rb1.y) * f1.y,
                        (v3.x + rb1.z) * f1.z, (v3.y + rb1.w) * f1.w);
    }
}

extern "C" void kernel_launch(void* const* d_in, const int* in_sizes, int n_in,
                              void* d_out, int out_size) {
    const float* x    = (const float*)d_in[0];
    const int*   ei   = (const int*)d_in[1];
    const int*   lbl  = (const int*)d_in[2];
    const int*   clen = (const int*)d_in[3];
    const float* gW   = (const float*)d_in[4];
    const float* gb   = (const float*)d_in[5];
    const float* rW   = (const float*)d_in[6];
    const float* rb   = (const float*)d_in[7];
    float* out = (float*)d_out;

    const int* src = ei;
    const int* dst = ei + NE;

    float *h, *f1, *f2, *inv, *csrc;
    int *cnt, *offs, *fill, *csrs, *perm, *lcnt, *loff, *lfill;
    cudaGetSymbolAddress((void**)&h,    d_h);
    cudaGetSymbolAddress((void**)&f1,   d_f1);
    cudaGetSymbolAddress((void**)&f2,   d_f2);
    cudaGetSymbolAddress((void**)&inv,  d_inv);
    cudaGetSymbolAddress((void**)&cnt,  d_cnt);
    cudaGetSymbolAddress((void**)&offs, d_offs);
    cudaGetSymbolAddress((void**)&fill, d_fill);
    cudaGetSymbolAddress((void**)&csrs, d_csrs);
    cudaGetSymbolAddress((void**)&csrc, d_csrc);
    cudaGetSymbolAddress((void**)&perm, d_perm);
    cudaGetSymbolAddress((void**)&lcnt, d_lcnt);
    cudaGetSymbolAddress((void**)&loff, d_loff);
    cudaGetSymbolAddress((void**)&lfill, d_lfill);

    const int BLK = 256;
    const int n_node_blk = (NN + BLK - 1) / BLK;
    const int n_edge_blk = (NE + BLK - 1) / BLK;
    const dim3 gemm_grid((NN + 127) / 128, 2);
    const int agg_blk = (NN * 32 + BLK - 1) / BLK;   // warp per node

    // CSR build + normalization + length-bucket sort
    k_zero<<<n_node_blk, BLK>>>(cnt, fill, lcnt, lfill);
    k_count<<<n_edge_blk, BLK>>>(dst, cnt);
    k_lcount<<<n_node_blk, BLK>>>(clen, lcnt);
    k_scan<<<1, 1024>>>(cnt, offs);
    k_lscan<<<1, 32>>>(lcnt, loff);
    k_invdeg<<<n_node_blk, BLK>>>(cnt, inv);
    k_fill<<<n_edge_blk, BLK>>>(src, dst, inv, offs, fill, csrs, csrc);
    k_lfill<<<n_node_blk, BLK>>>(clen, loff, lfill, perm);

    // layer 1
    sgemm_nn<<<gemm_grid, 256>>>(x, gW, h, NN);
    k_aggregate<<<agg_blk, BLK>>>(h, gb, inv, offs, cnt, csrs, csrc, f1, 1);
    // layer 2
    sgemm_nn<<<gemm_grid, 256>>>(f1, gW, h, NN);
    k_aggregate<<<agg_blk, BLK>>>(h, gb, inv, offs, cnt, csrs, csrc, f2, 0);
    // fused context-gather resize GEMM (length-sorted) + final product
    sgemm_gather<<<gemm_grid, 256>>>(f2, lbl, clen, perm, rW, rb, out, NN);
}